// round 1
// baseline (speedup 1.0000x reference)
#include <cuda_runtime.h>
#include <cmath>

// Problem constants
#define Bq   2
#define Cq   64
#define Sq   325
#define Tq   12
#define Mq   650          // B*S
#define DMq  256
#define Pq   32
#define IN1q 768
#define OUT2q 768
#define JWq  196608       // DM*IN1 == OUT2*DM

// ---------------- scratch (device globals; no allocation allowed) ----------------
__device__ float g_scale[Tq];
__device__ float g_shift[Tq];
__device__ float g_y[Mq * IN1q];        // 2 MB
__device__ float g_a1[Mq * Pq];
__device__ float g_a2[Mq * Pq];
__device__ float g_hpre[Mq * DMq];      // b1 mixed bias
__device__ float g_h[Mq * DMq];         // relu(h)
__device__ float g_zpre[Mq * OUT2q];    // b2 mixed bias

// ---------------- BN stats: one block per t channel ----------------
__global__ void bn_stats_kernel(const float* __restrict__ x,
                                const float* __restrict__ gamma,
                                const float* __restrict__ beta) {
    const int t = blockIdx.x;
    const int tid = threadIdx.x;
    const int N = Bq * Cq * Sq;  // 41600
    float s = 0.f, s2 = 0.f;
    for (int i = tid; i < N; i += 256) {
        float v = x[(size_t)i * Tq + t];
        s += v; s2 += v * v;
    }
    __shared__ float rs[256], rq[256];
    rs[tid] = s; rq[tid] = s2; __syncthreads();
    for (int o = 128; o; o >>= 1) {
        if (tid < o) { rs[tid] += rs[tid + o]; rq[tid] += rq[tid + o]; }
        __syncthreads();
    }
    if (tid == 0) {
        float mean = rs[0] / (float)N;
        float var  = rq[0] / (float)N - mean * mean;
        float rstd = rsqrtf(var + 1e-5f);
        float sc = gamma[t] * rstd;
        g_scale[t] = sc;
        g_shift[t] = beta[t] - mean * sc;
    }
}

// ---------------- y = BN(x) reshaped to [M, 768] with j = t*64 + c ----------------
__global__ void make_y_kernel(const float* __restrict__ x) {
    const int m = blockIdx.x, j = threadIdx.x;
    const int t = j >> 6, c = j & 63;
    const int b = m / Sq, s = m % Sq;
    float v = x[(((size_t)(b * Cq + c)) * Sq + s) * Tq + t];
    g_y[(size_t)m * IN1q + j] = v * g_scale[t] + g_shift[t];
}

// ---------------- cosine-similarity softmax attention over P keys ----------------
template <int D>
__device__ __forceinline__ void attn_body(const float* __restrict__ Y,
                                          const float* __restrict__ keys,
                                          float* __restrict__ Aout) {
    const int m = blockIdx.x;
    __shared__ float ysm[D];
    __shared__ float sims[Pq];
    __shared__ float red[8];
    const int tid = threadIdx.x;
    for (int i = tid; i < D; i += 256) ysm[i] = Y[(size_t)m * D + i];
    __syncthreads();
    float ss = 0.f;
    for (int i = tid; i < D; i += 256) { float v = ysm[i]; ss += v * v; }
    for (int o = 16; o; o >>= 1) ss += __shfl_down_sync(0xffffffffu, ss, o);
    if ((tid & 31) == 0) red[tid >> 5] = ss;
    __syncthreads();
    float ysq = red[0] + red[1] + red[2] + red[3] + red[4] + red[5] + red[6] + red[7];
    float yn = sqrtf(ysq);
    const int w = tid >> 5, l = tid & 31;
    for (int p = w; p < Pq; p += 8) {
        float dot = 0.f, ksq = 0.f;
        for (int i = l; i < D; i += 32) {
            float kv = keys[(size_t)p * D + i];
            dot += ysm[i] * kv;
            ksq += kv * kv;
        }
        for (int o = 16; o; o >>= 1) {
            dot += __shfl_down_sync(0xffffffffu, dot, o);
            ksq += __shfl_down_sync(0xffffffffu, ksq, o);
        }
        if (l == 0) sims[p] = dot / fmaxf(yn * sqrtf(ksq), 1e-8f);
    }
    __syncthreads();
    if (tid < 32) {
        float v = sims[tid];
        float mx = v;
        for (int o = 16; o; o >>= 1) mx = fmaxf(mx, __shfl_xor_sync(0xffffffffu, mx, o));
        float e = expf(v - mx);
        float sum = e;
        for (int o = 16; o; o >>= 1) sum += __shfl_xor_sync(0xffffffffu, sum, o);
        Aout[m * Pq + tid] = e / sum;
    }
}
__global__ void attn1_kernel(const float* __restrict__ keys1) { attn_body<IN1q>(g_y, keys1, g_a1); }
__global__ void attn2_kernel(const float* __restrict__ keys2) { attn_body<DMq>(g_h, keys2, g_a2); }

// ---------------- bias mixing: out[m,n] = sum_p A[m,p] * Bp[p,n] ----------------
__device__ __forceinline__ void biasmix_body(const float* __restrict__ A,
                                             const float* __restrict__ Bp,
                                             float* __restrict__ out, int N) {
    const int m = blockIdx.x, tid = threadIdx.x;
    __shared__ float a_sm[Pq];
    if (tid < Pq) a_sm[tid] = A[m * Pq + tid];
    __syncthreads();
    for (int n = tid; n < N; n += blockDim.x) {
        float acc = 0.f;
        #pragma unroll
        for (int p = 0; p < Pq; p++) acc = fmaf(a_sm[p], Bp[p * N + n], acc);
        out[(size_t)m * N + n] = acc;
    }
}
__global__ void bias1_kernel(const float* __restrict__ pb1) { biasmix_body(g_a1, pb1, g_hpre, DMq); }
__global__ void bias2_kernel(const float* __restrict__ pb2) { biasmix_body(g_a2, pb2, g_zpre, OUT2q); }

// ---------------- the big one: out[m, cb + c] = sum_p A[m,p] * W[p, cb + c] ----------------
// Grid: (256 column tiles of 768, 5 row blocks of 130). 96 KB dynamic smem W tile,
// amortized across 130 rows -> W read only ~5x total (stays out of L2-bound regime).
// Per thread: 3 columns x 8-row register block -> 96 FMA per 20 LDS -> FMA-pipe bound.
__device__ __forceinline__ void poolmix_body(const float* __restrict__ A,
                                             const float* __restrict__ W,
                                             float* __restrict__ out) {
    extern __shared__ float Wsm[];          // [32][768] = 96 KB
    __shared__ float a_sm[8 * Pq];          // 8 rows of a-weights
    const int tid = threadIdx.x;
    const int cb = blockIdx.x * 768;

    for (int i = tid; i < Pq * 768 / 4; i += 256) {
        int p  = i / 192;   // 768/4 float4 per row
        int t4 = i % 192;
        ((float4*)Wsm)[i] = __ldg((const float4*)(W + (size_t)p * JWq + cb) + t4);
    }
    const int row0 = blockIdx.y * 130;
    const int row_end = row0 + 130;         // 5*130 = 650 exact
    __syncthreads();

    const int t0 = tid;
    for (int r0 = row0; r0 < row_end; r0 += 8) {
        const int nr = min(8, row_end - r0);
        __syncthreads();                    // protect a_sm reuse
        if (tid < nr * Pq) a_sm[tid] = A[r0 * Pq + tid];
        __syncthreads();

        if (nr == 8) {
            float acc0[8], acc1[8], acc2[8];
            #pragma unroll
            for (int r = 0; r < 8; r++) { acc0[r] = 0.f; acc1[r] = 0.f; acc2[r] = 0.f; }
            #pragma unroll
            for (int p4 = 0; p4 < Pq; p4 += 4) {
                float4 av[8];
                #pragma unroll
                for (int r = 0; r < 8; r++) av[r] = ((const float4*)a_sm)[r * 8 + (p4 >> 2)];
                #pragma unroll
                for (int pp = 0; pp < 4; pp++) {
                    const float w0  = Wsm[(p4 + pp) * 768 + t0];
                    const float w1v = Wsm[(p4 + pp) * 768 + t0 + 256];
                    const float w2v = Wsm[(p4 + pp) * 768 + t0 + 512];
                    #pragma unroll
                    for (int r = 0; r < 8; r++) {
                        const float a = (pp == 0) ? av[r].x : (pp == 1) ? av[r].y
                                     : (pp == 2) ? av[r].z : av[r].w;
                        acc0[r] = fmaf(a, w0,  acc0[r]);
                        acc1[r] = fmaf(a, w1v, acc1[r]);
                        acc2[r] = fmaf(a, w2v, acc2[r]);
                    }
                }
            }
            #pragma unroll
            for (int r = 0; r < 8; r++) {
                float* o = out + (size_t)(r0 + r) * JWq + cb;
                o[t0] = acc0[r]; o[t0 + 256] = acc1[r]; o[t0 + 512] = acc2[r];
            }
        } else {
            for (int r = 0; r < nr; r++) {
                float acc0 = 0.f, acc1 = 0.f, acc2 = 0.f;
                #pragma unroll
                for (int p = 0; p < Pq; p++) {
                    const float a = a_sm[r * Pq + p];
                    acc0 = fmaf(a, Wsm[p * 768 + t0],       acc0);
                    acc1 = fmaf(a, Wsm[p * 768 + t0 + 256], acc1);
                    acc2 = fmaf(a, Wsm[p * 768 + t0 + 512], acc2);
                }
                float* o = out + (size_t)(r0 + r) * JWq + cb;
                o[t0] = acc0; o[t0 + 256] = acc1; o[t0 + 512] = acc2;
            }
        }
    }
}
__global__ void __launch_bounds__(256, 2)
poolmix1_kernel(const float* __restrict__ W, float* __restrict__ out) { poolmix_body(g_a1, W, out); }
__global__ void __launch_bounds__(256, 2)
poolmix2_kernel(const float* __restrict__ W, float* __restrict__ out) { poolmix_body(g_a2, W, out); }

// ---------------- h[m,d] = relu(b1 + sum_t y[m,t] * w1[m,d,t]) ----------------
__global__ void hcompute_kernel(const float* __restrict__ w1) {
    const int m = blockIdx.y;
    __shared__ float ysm[IN1q];
    const int tid = threadIdx.x;
    for (int i = tid; i < IN1q; i += 256) ysm[i] = g_y[(size_t)m * IN1q + i];
    __syncthreads();
    const int w = tid >> 5, l = tid & 31;
    const int d = blockIdx.x * 8 + w;
    const float4* row = (const float4*)(w1 + (size_t)m * JWq + (size_t)d * IN1q);
    const float4* y4 = (const float4*)ysm;
    float dot = 0.f;
    #pragma unroll
    for (int i = 0; i < 6; i++) {
        float4 wv = __ldg(row + l + 32 * i);
        float4 yy = y4[l + 32 * i];
        dot += wv.x * yy.x + wv.y * yy.y + wv.z * yy.z + wv.w * yy.w;
    }
    for (int o = 16; o; o >>= 1) dot += __shfl_down_sync(0xffffffffu, dot, o);
    if (l == 0) g_h[m * DMq + d] = fmaxf(g_hpre[m * DMq + d] + dot, 0.f);
}

// ---------------- z[m,tout] = b2 + sum_d h[m,d]*w2[m,tout,d]; out0 = x + z ----------------
__global__ void zout_kernel(const float* __restrict__ w2, const float* __restrict__ x,
                            float* __restrict__ out0) {
    const int m = blockIdx.y;
    __shared__ float hsm[DMq];
    const int tid = threadIdx.x;
    hsm[tid] = g_h[m * DMq + tid];
    __syncthreads();
    const int w = tid >> 5, l = tid & 31;
    const int tout = blockIdx.x * 8 + w;
    const float4* row = (const float4*)(w2 + (size_t)m * JWq + (size_t)tout * DMq);
    const float4* h4 = (const float4*)hsm;
    float dot = 0.f;
    #pragma unroll
    for (int i = 0; i < 2; i++) {
        float4 wv = __ldg(row + l + 32 * i);
        float4 hh = h4[l + 32 * i];
        dot += wv.x * hh.x + wv.y * hh.y + wv.z * hh.z + wv.w * hh.w;
    }
    for (int o = 16; o; o >>= 1) dot += __shfl_down_sync(0xffffffffu, dot, o);
    if (l == 0) {
        const int t = tout >> 6, c = tout & 63;
        const int b = m / Sq, s = m % Sq;
        const size_t xi = (((size_t)(b * Cq + c)) * Sq + s) * Tq + t;
        out0[xi] = x[xi] + g_zpre[m * OUT2q + tout] + dot;
    }
}

// ---------------- launch ----------------
extern "C" void kernel_launch(void* const* d_in, const int* in_sizes, int n_in,
                              void* d_out, int out_size) {
    const float* x     = (const float*)d_in[0];
    const float* gamma = (const float*)d_in[1];
    const float* beta  = (const float*)d_in[2];
    const float* keys1 = (const float*)d_in[3];
    const float* pw1   = (const float*)d_in[4];
    const float* pb1   = (const float*)d_in[5];
    const float* keys2 = (const float*)d_in[6];
    const float* pw2   = (const float*)d_in[7];
    const float* pb2   = (const float*)d_in[8];

    float* out0 = (float*)d_out;                       // [B,C,S,T] = 499200
    float* w1o  = out0 + (size_t)Bq * Cq * Sq * Tq;    // [B,S,DM,IN1]
    float* w2o  = w1o + (size_t)Mq * JWq;              // [B,S,OUT2,DM]

    // 96 KB dynamic smem opt-in (idempotent; safe to call every invocation)
    cudaFuncSetAttribute(poolmix1_kernel, cudaFuncAttributeMaxDynamicSharedMemorySize, 98304);
    cudaFuncSetAttribute(poolmix2_kernel, cudaFuncAttributeMaxDynamicSharedMemorySize, 98304);

    bn_stats_kernel<<<Tq, 256>>>(x, gamma, beta);
    make_y_kernel<<<Mq, IN1q>>>(x);
    attn1_kernel<<<Mq, 256>>>(keys1);
    bias1_kernel<<<Mq, 256>>>(pb1);
    poolmix1_kernel<<<dim3(DMq, 5), 256, 98304>>>(pw1, w1o);
    hcompute_kernel<<<dim3(32, Mq), 256>>>(w1o);
    attn2_kernel<<<Mq, 256>>>(keys2);
    bias2_kernel<<<Mq, 256>>>(pb2);
    poolmix2_kernel<<<dim3(DMq, 5), 256, 98304>>>(pw2, w2o);
    zout_kernel<<<dim3(96, Mq), 256>>>(w2o, x, out0);
}

// round 2
// speedup vs baseline: 1.1384x; 1.1384x over previous
#include <cuda_runtime.h>
#include <cstdint>
#include <cmath>

typedef unsigned long long ull;

// Problem constants
#define Bq   2
#define Cq   64
#define Sq   325
#define Tq   12
#define Mq   650          // B*S
#define DMq  256
#define Pq   32
#define IN1q 768
#define OUT2q 768
#define JWq  196608       // DM*IN1 == OUT2*DM

// ---------------- scratch (device globals; no allocation allowed) ----------------
__device__ float g_scale[Tq];
__device__ float g_shift[Tq];
__device__ float g_y[Mq * IN1q];        // 2 MB
__device__ float g_a1[Mq * Pq];
__device__ float g_a2[Mq * Pq];
__device__ float g_hpre[Mq * DMq];      // b1 mixed bias
__device__ float g_h[Mq * DMq];         // relu(h)
__device__ float g_zpre[Mq * OUT2q];    // b2 mixed bias

// ---------------- f32x2 helpers ----------------
__device__ __forceinline__ ull bcast2(float v) {
    ull r; asm("mov.b64 %0, {%1,%1};" : "=l"(r) : "f"(v)); return r;
}
__device__ __forceinline__ void unpk2(ull v, float& lo, float& hi) {
    asm("mov.b64 {%0,%1}, %2;" : "=f"(lo), "=f"(hi) : "l"(v));
}

// ---------------- BN stats: one block per t channel ----------------
__global__ void bn_stats_kernel(const float* __restrict__ x,
                                const float* __restrict__ gamma,
                                const float* __restrict__ beta) {
    const int t = blockIdx.x;
    const int tid = threadIdx.x;
    const int N = Bq * Cq * Sq;  // 41600
    float s = 0.f, s2 = 0.f;
    for (int i = tid; i < N; i += 256) {
        float v = x[(size_t)i * Tq + t];
        s += v; s2 += v * v;
    }
    __shared__ float rs[256], rq[256];
    rs[tid] = s; rq[tid] = s2; __syncthreads();
    for (int o = 128; o; o >>= 1) {
        if (tid < o) { rs[tid] += rs[tid + o]; rq[tid] += rq[tid + o]; }
        __syncthreads();
    }
    if (tid == 0) {
        float mean = rs[0] / (float)N;
        float var  = rq[0] / (float)N - mean * mean;
        float rstd = rsqrtf(var + 1e-5f);
        float sc = gamma[t] * rstd;
        g_scale[t] = sc;
        g_shift[t] = beta[t] - mean * sc;
    }
}

// ---------------- y = BN(x) reshaped to [M, 768] with j = t*64 + c ----------------
__global__ void make_y_kernel(const float* __restrict__ x) {
    const int m = blockIdx.x, j = threadIdx.x;
    const int t = j >> 6, c = j & 63;
    const int b = m / Sq, s = m % Sq;
    float v = x[(((size_t)(b * Cq + c)) * Sq + s) * Tq + t];
    g_y[(size_t)m * IN1q + j] = v * g_scale[t] + g_shift[t];
}

// ---------------- fused cosine-attn softmax + bias mix ----------------
template <int D, int NB>
__device__ __forceinline__ void attn_bias_body(const float* __restrict__ Y,
                                               const float* __restrict__ keys,
                                               const float* __restrict__ Bp,
                                               float* __restrict__ Aout,
                                               float* __restrict__ BiasOut) {
    const int m = blockIdx.x;
    __shared__ float ysm[D];
    __shared__ float sims[Pq];
    __shared__ float red[8];
    __shared__ float a_sm[Pq];
    const int tid = threadIdx.x;
    for (int i = tid; i < D; i += 256) ysm[i] = Y[(size_t)m * D + i];
    __syncthreads();
    float ss = 0.f;
    for (int i = tid; i < D; i += 256) { float v = ysm[i]; ss += v * v; }
    for (int o = 16; o; o >>= 1) ss += __shfl_down_sync(0xffffffffu, ss, o);
    if ((tid & 31) == 0) red[tid >> 5] = ss;
    __syncthreads();
    float ysq = red[0] + red[1] + red[2] + red[3] + red[4] + red[5] + red[6] + red[7];
    float yn = sqrtf(ysq);
    const int w = tid >> 5, l = tid & 31;
    for (int p = w; p < Pq; p += 8) {
        float dot = 0.f, ksq = 0.f;
        for (int i = l; i < D; i += 32) {
            float kv = keys[(size_t)p * D + i];
            dot += ysm[i] * kv;
            ksq += kv * kv;
        }
        for (int o = 16; o; o >>= 1) {
            dot += __shfl_down_sync(0xffffffffu, dot, o);
            ksq += __shfl_down_sync(0xffffffffu, ksq, o);
        }
        if (l == 0) sims[p] = dot / fmaxf(yn * sqrtf(ksq), 1e-8f);
    }
    __syncthreads();
    if (tid < 32) {
        float v = sims[tid];
        float mx = v;
        for (int o = 16; o; o >>= 1) mx = fmaxf(mx, __shfl_xor_sync(0xffffffffu, mx, o));
        float e = expf(v - mx);
        float sum = e;
        for (int o = 16; o; o >>= 1) sum += __shfl_xor_sync(0xffffffffu, sum, o);
        float a = e / sum;
        a_sm[tid] = a;
        Aout[m * Pq + tid] = a;
    }
    __syncthreads();
    // bias mix: BiasOut[m, n] = sum_p a[p] * Bp[p, n]
    #pragma unroll
    for (int nb = 0; nb < NB; nb++) {
        int n = tid + nb * 256;
        float acc = 0.f;
        #pragma unroll
        for (int p = 0; p < Pq; p++) acc = fmaf(a_sm[p], Bp[p * (NB * 256) + n], acc);
        BiasOut[(size_t)m * (NB * 256) + n] = acc;
    }
}
__global__ void attn1bias1_kernel(const float* __restrict__ keys1, const float* __restrict__ pb1) {
    attn_bias_body<IN1q, 1>(g_y, keys1, pb1, g_a1, g_hpre);
}
__global__ void attn2bias2_kernel(const float* __restrict__ keys2, const float* __restrict__ pb2) {
    attn_bias_body<DMq, 3>(g_h, keys2, pb2, g_a2, g_zpre);
}

// ---------------- packed-FMA accumulation core ----------------
// acc[c][q] accumulates rows (2q, 2q+1) for column t0 + c*256, over p = 0..31.
// a-tile layout: a_smT[p*NR + r] (row pairs contiguous -> direct b64 loads).
template <int NRP>
__device__ __forceinline__ void accum_loop(const float* __restrict__ Wsm,
                                           uint32_t a_base, int t0,
                                           ull (&acc)[3][NRP]) {
    #pragma unroll
    for (int c = 0; c < 3; c++)
        #pragma unroll
        for (int q = 0; q < NRP; q++) acc[c][q] = 0ull;

    #pragma unroll
    for (int p = 0; p < Pq; p++) {
        float w0  = Wsm[p * 768 + t0];
        float w1v = Wsm[p * 768 + t0 + 256];
        float w2v = Wsm[p * 768 + t0 + 512];
        ull wp0 = bcast2(w0), wp1 = bcast2(w1v), wp2 = bcast2(w2v);
        ull ap[NRP];
        uint32_t ab = a_base + (uint32_t)(p * NRP * 8);
        if constexpr ((NRP & 1) == 0) {
            #pragma unroll
            for (int q = 0; q < NRP; q += 2)
                asm volatile("ld.shared.v2.u64 {%0,%1}, [%2];"
                             : "=l"(ap[q]), "=l"(ap[q + 1]) : "r"(ab + q * 8));
        } else {
            #pragma unroll
            for (int q = 0; q < NRP; q++)
                asm volatile("ld.shared.u64 %0, [%1];" : "=l"(ap[q]) : "r"(ab + q * 8));
        }
        #pragma unroll
        for (int q = 0; q < NRP; q++) {
            asm("fma.rn.f32x2 %0, %1, %2, %0;" : "+l"(acc[0][q]) : "l"(ap[q]), "l"(wp0));
            asm("fma.rn.f32x2 %0, %1, %2, %0;" : "+l"(acc[1][q]) : "l"(ap[q]), "l"(wp1));
            asm("fma.rn.f32x2 %0, %1, %2, %0;" : "+l"(acc[2][q]) : "l"(ap[q]), "l"(wp2));
        }
    }
}

// ---------------- poolmix1 + fused h = relu(b1mix + y . w1row) ----------------
// Block bx = d; columns cover w1[m, d, 0..767]; h[m,d] reduction lives entirely here.
template <int NR>
__device__ __forceinline__ void chunk1(const float* __restrict__ Wsm,
                                       float* __restrict__ a_smT, uint32_t a_base,
                                       float* __restrict__ redsm,
                                       int r0, int t0, int d,
                                       float* __restrict__ out) {
    constexpr int NRP = NR / 2;
    __syncthreads();  // a_smT / redsm safe to overwrite
    for (int i = t0; i < NR * Pq; i += 256) {
        int r = i >> 5, p = i & 31;
        a_smT[p * NR + r] = g_a1[(r0 + r) * Pq + p];
    }
    __syncthreads();

    ull acc[3][NRP];
    accum_loop<NRP>(Wsm, a_base, t0, acc);

    float f0[NR], f1[NR], f2[NR];
    #pragma unroll
    for (int q = 0; q < NRP; q++) {
        unpk2(acc[0][q], f0[2 * q], f0[2 * q + 1]);
        unpk2(acc[1][q], f1[2 * q], f1[2 * q + 1]);
        unpk2(acc[2][q], f2[2 * q], f2[2 * q + 1]);
    }
    const int warp = t0 >> 5, lane = t0 & 31;
    #pragma unroll
    for (int r = 0; r < NR; r++) {
        const int m = r0 + r;
        float* o = out + (size_t)m * JWq + (size_t)d * 768;
        o[t0] = f0[r]; o[t0 + 256] = f1[r]; o[t0 + 512] = f2[r];
        const float* yr = g_y + (size_t)m * IN1q;
        float pr = f0[r] * yr[t0] + f1[r] * yr[t0 + 256] + f2[r] * yr[t0 + 512];
        #pragma unroll
        for (int o2 = 16; o2; o2 >>= 1) pr += __shfl_down_sync(0xffffffffu, pr, o2);
        if (lane == 0) redsm[r * 8 + warp] = pr;
    }
    __syncthreads();
    if (t0 < NR * 8) {
        constexpr unsigned fmask = (NR * 8 >= 32) ? 0xffffffffu : ((1u << (NR * 8)) - 1u);
        float v = redsm[t0];
        v += __shfl_down_sync(fmask, v, 4, 8);
        v += __shfl_down_sync(fmask, v, 2, 8);
        v += __shfl_down_sync(fmask, v, 1, 8);
        if ((t0 & 7) == 0) {
            int m = r0 + (t0 >> 3);
            g_h[m * DMq + d] = fmaxf(g_hpre[m * DMq + d] + v, 0.f);
        }
    }
}

__global__ void __launch_bounds__(256, 2)
poolmix1h_kernel(const float* __restrict__ W, float* __restrict__ out) {
    extern __shared__ float Wsm[];          // [32][768] = 96 KB
    __shared__ float a_smT[Pq * 16];
    __shared__ float redsm[16 * 3 * 8];
    const int tid = threadIdx.x;
    const int d = blockIdx.x;
    const int cb = d * 768;
    for (int i = tid; i < Pq * 192; i += 256) {
        int p = i / 192, t4 = i % 192;
        ((float4*)Wsm)[i] = __ldg((const float4*)(W + (size_t)p * JWq + cb) + t4);
    }
    uint32_t a_base = (uint32_t)__cvta_generic_to_shared(a_smT);
    const int row0 = blockIdx.y * 130;
    for (int r0 = row0; r0 < row0 + 128; r0 += 16)
        chunk1<16>(Wsm, a_smT, a_base, redsm, r0, tid, d, out);
    chunk1<2>(Wsm, a_smT, a_base, redsm, row0 + 128, tid, d, out);
}

// ---------------- poolmix2 + fused z = b2mix + h . w2row; out0 = x + z ----------------
// Block bx covers touts 3bx..3bx+2, all dd in 0..255.
template <int NR>
__device__ __forceinline__ void chunk2(const float* __restrict__ Wsm,
                                       float* __restrict__ a_smT, uint32_t a_base,
                                       float* __restrict__ redsm,
                                       int r0, int t0, int bx,
                                       float* __restrict__ w2out,
                                       const float* __restrict__ x,
                                       float* __restrict__ out0) {
    constexpr int NRP = NR / 2;
    __syncthreads();
    for (int i = t0; i < NR * Pq; i += 256) {
        int r = i >> 5, p = i & 31;
        a_smT[p * NR + r] = g_a2[(r0 + r) * Pq + p];
    }
    __syncthreads();

    ull acc[3][NRP];
    accum_loop<NRP>(Wsm, a_base, t0, acc);

    float f0[NR], f1[NR], f2[NR];
    #pragma unroll
    for (int q = 0; q < NRP; q++) {
        unpk2(acc[0][q], f0[2 * q], f0[2 * q + 1]);
        unpk2(acc[1][q], f1[2 * q], f1[2 * q + 1]);
        unpk2(acc[2][q], f2[2 * q], f2[2 * q + 1]);
    }
    const int warp = t0 >> 5, lane = t0 & 31;
    #pragma unroll
    for (int r = 0; r < NR; r++) {
        const int m = r0 + r;
        float* o = w2out + (size_t)m * JWq + (size_t)bx * 768;
        o[t0] = f0[r]; o[t0 + 256] = f1[r]; o[t0 + 512] = f2[r];
        const float hv = g_h[m * DMq + t0];
        float p0 = f0[r] * hv, p1 = f1[r] * hv, p2 = f2[r] * hv;
        #pragma unroll
        for (int o2 = 16; o2; o2 >>= 1) {
            p0 += __shfl_down_sync(0xffffffffu, p0, o2);
            p1 += __shfl_down_sync(0xffffffffu, p1, o2);
            p2 += __shfl_down_sync(0xffffffffu, p2, o2);
        }
        if (lane == 0) {
            redsm[(r * 3 + 0) * 8 + warp] = p0;
            redsm[(r * 3 + 1) * 8 + warp] = p1;
            redsm[(r * 3 + 2) * 8 + warp] = p2;
        }
    }
    __syncthreads();
    for (int idx = t0; idx < NR * 3; idx += 256) {
        float s = 0.f;
        #pragma unroll
        for (int w = 0; w < 8; w++) s += redsm[idx * 8 + w];
        const int r = idx / 3, k = idx % 3;
        const int m = r0 + r;
        const int tout = 3 * bx + k;
        float z = s + g_zpre[(size_t)m * OUT2q + tout];
        const int t = tout >> 6, c = tout & 63;
        const int b = m / Sq, si = m % Sq;
        const size_t xi = (((size_t)(b * Cq + c)) * Sq + si) * Tq + t;
        out0[xi] = x[xi] + z;
    }
}

__global__ void __launch_bounds__(256, 2)
poolmix2z_kernel(const float* __restrict__ W, float* __restrict__ w2out,
                 const float* __restrict__ x, float* __restrict__ out0) {
    extern __shared__ float Wsm[];
    __shared__ float a_smT[Pq * 16];
    __shared__ float redsm[16 * 3 * 8];
    const int tid = threadIdx.x;
    const int bx = blockIdx.x;
    const int cb = bx * 768;
    for (int i = tid; i < Pq * 192; i += 256) {
        int p = i / 192, t4 = i % 192;
        ((float4*)Wsm)[i] = __ldg((const float4*)(W + (size_t)p * JWq + cb) + t4);
    }
    uint32_t a_base = (uint32_t)__cvta_generic_to_shared(a_smT);
    const int row0 = blockIdx.y * 130;
    for (int r0 = row0; r0 < row0 + 128; r0 += 16)
        chunk2<16>(Wsm, a_smT, a_base, redsm, r0, tid, bx, w2out, x, out0);
    chunk2<2>(Wsm, a_smT, a_base, redsm, row0 + 128, tid, bx, w2out, x, out0);
}

// ---------------- launch ----------------
extern "C" void kernel_launch(void* const* d_in, const int* in_sizes, int n_in,
                              void* d_out, int out_size) {
    const float* x     = (const float*)d_in[0];
    const float* gamma = (const float*)d_in[1];
    const float* beta  = (const float*)d_in[2];
    const float* keys1 = (const float*)d_in[3];
    const float* pw1   = (const float*)d_in[4];
    const float* pb1   = (const float*)d_in[5];
    const float* keys2 = (const float*)d_in[6];
    const float* pw2   = (const float*)d_in[7];
    const float* pb2   = (const float*)d_in[8];

    float* out0 = (float*)d_out;                       // [B,C,S,T] = 499200
    float* w1o  = out0 + (size_t)Bq * Cq * Sq * Tq;    // [B,S,DM,IN1]
    float* w2o  = w1o + (size_t)Mq * JWq;              // [B,S,OUT2,DM]

    cudaFuncSetAttribute(poolmix1h_kernel, cudaFuncAttributeMaxDynamicSharedMemorySize, 98304);
    cudaFuncSetAttribute(poolmix2z_kernel, cudaFuncAttributeMaxDynamicSharedMemorySize, 98304);

    bn_stats_kernel<<<Tq, 256>>>(x, gamma, beta);
    make_y_kernel<<<Mq, IN1q>>>(x);
    attn1bias1_kernel<<<Mq, 256>>>(keys1, pb1);
    poolmix1h_kernel<<<dim3(DMq, 5), 256, 98304>>>(pw1, w1o);
    attn2bias2_kernel<<<Mq, 256>>>(keys2, pb2);
    poolmix2z_kernel<<<dim3(DMq, 5), 256, 98304>>>(pw2, w2o, x, out0);
}